// round 14
// baseline (speedup 1.0000x reference)
#include <cuda_runtime.h>
#include <cstdint>

#define HD   128
#define TS   512
#define BSZ  4096
#define CD   10
#define BT   32
#define NCTA (BSZ / BT)   // 128
#define NTHR 512          // 16 warps = 8 pairs; pair p owns cols 4p..4p+3
#define TPREF 128
#define TSAT 9.2f         // fp32 tanhf(x) == 1.0f for x >= ~9.01 (margin kept)

// ---- shared memory layout (bytes) ----
#define SM_W    0                    // W[m][k] swizzled, row 512B : 64 KB
#define SM_X    (64 * 1024)          // xs[32][TPREF]              : 16 KB
#define SM_H    (80 * 1024)          // h[2][32][128] ping-pong    : 32 KB
#define SM_RS   (112 * 1024)         // rowsum[128]                : 512 B
#define SM_F    (SM_RS + 512)        // sflag, cert scalars
#define SM_SZ   (SM_F + 256)

typedef unsigned long long ull;

static __device__ __forceinline__ ull pk(float lo, float hi) {
    ull r; asm("mov.b64 %0, {%1, %2};" : "=l"(r) : "f"(lo), "f"(hi)); return r;
}
static __device__ __forceinline__ void upk(ull v, float& lo, float& hi) {
    asm("mov.b64 {%0, %1}, %2;" : "=f"(lo), "=f"(hi) : "l"(v));
}
static __device__ __forceinline__ ull fma2(ull a, ull b, ull c) {
    ull d; asm("fma.rn.f32x2 %0, %1, %2, %3;" : "=l"(d) : "l"(a), "l"(b), "l"(c)); return d;
}
static __device__ __forceinline__ ull add2(ull a, ull b) {
    ull d; asm("add.rn.f32x2 %0, %1, %2;" : "=l"(d) : "l"(a), "l"(b)); return d;
}
// exactly +-1.0f for |x| >~ 9 (matches fp32 tanhf saturation); ~1e-7 abs err
// __fdividef: 2/(inf) -> 0, so saturation to exactly 1.0f is preserved.
static __device__ __forceinline__ float tanh_acc(float v) {
    float a = fabsf(v);
    float e = __expf(2.0f * a);
    float r = 1.0f - __fdividef(2.0f, e + 1.0f);
    return copysignf(r, v);
}

// epilogue: tanh, float2 write of this half's m-pair, per-col threshold
// votes. am bits: j -> all v >= thr[j] ; 8+j -> all v <= -thr[j]
template <int J>
static __device__ __forceinline__ unsigned
epilogue(const ull* acc, float* hwr, const int* cols, int mb, const float* thr)
{
    unsigned am = 0;
    #pragma unroll
    for (int j = 0; j < J; ++j) {
        float v0, v1; upk(acc[j], v0, v1);
        v0 = tanh_acc(v0); v1 = tanh_acc(v1);
        *(float2*)(hwr + cols[j] * HD + mb) = make_float2(v0, v1);
        bool p = (v0 >=  thr[j]) & (v1 >=  thr[j]);
        bool n = (v0 <= -thr[j]) & (v1 <= -thr[j]);
        unsigned bp_ = __ballot_sync(0xffffffffu, p);
        unsigned bn_ = __ballot_sync(0xffffffffu, n);
        if (bp_ == 0xffffffffu) am |= 1u << j;
        if (bn_ == 0xffffffffu) am |= 1u << (8 + j);
    }
    return am;
}

// one step for J live columns; this warp covers m = mb, mb+1 (its half).
// k-vectorized: acc lanes are (even-k, odd-k) partial sums; horizontal add
// at the end. J=2: 2 chains; J=1: 4 chains (shortest serial tail).
template <int J>
static __device__ __forceinline__ unsigned
do_step(const char* Wp, uint32_t wsw, const float* hrd, float* hwr,
        const int* cols, const float* xv,
        float wx0, float wx1, float bh0, float bh1, int mb, const float* thr)
{
    constexpr int CH = (J == 1) ? 4 : ((J == 2) ? 2 : 1);
    ull a0[J][CH], a1[J][CH];          // rows mb, mb+1
    const float* hc[J];
    #pragma unroll
    for (int j = 0; j < J; ++j) {
        a0[j][0] = pk(fmaf(wx0, xv[j], bh0), 0.0f);   // x-term+bias in .lo
        a1[j][0] = pk(fmaf(wx1, xv[j], bh1), 0.0f);
        #pragma unroll
        for (int c = 1; c < CH; ++c) { a0[j][c] = 0ull; a1[j][c] = 0ull; }
        hc[j] = hrd + cols[j] * HD;
    }
    #pragma unroll 4
    for (int k4 = 0; k4 < 32; ++k4) {
        const int ch = k4 & (CH - 1);
        const uint32_t woff = ((uint32_t)(k4 << 4)) ^ wsw;   // swizzled 16B slot
        const ulonglong2 w0 = *(const ulonglong2*)(Wp + woff);        // row mb
        const ulonglong2 w1 = *(const ulonglong2*)(Wp + 512 + woff);  // row mb+1
        #pragma unroll
        for (int j = 0; j < J; ++j) {
            const ulonglong2 h = *(const ulonglong2*)(hc[j] + 4 * k4); // bcast
            a0[j][ch] = fma2(w0.x, h.x, a0[j][ch]);
            a0[j][ch] = fma2(w0.y, h.y, a0[j][ch]);
            a1[j][ch] = fma2(w1.x, h.x, a1[j][ch]);
            a1[j][ch] = fma2(w1.y, h.y, a1[j][ch]);
        }
    }
    ull fin[J];
    #pragma unroll
    for (int j = 0; j < J; ++j) {
        ull f0 = a0[j][0], f1 = a1[j][0];
        #pragma unroll
        for (int c = 1; c < CH; ++c) { f0 = add2(f0, a0[j][c]); f1 = add2(f1, a1[j][c]); }
        float p0, p1, q0, q1;
        upk(f0, p0, p1); upk(f1, q0, q1);
        fin[j] = pk(p0 + p1, q0 + q1);               // horizontal reduce
    }
    return epilogue<J>(fin, hwr, cols, mb, thr);
}

__global__ void __launch_bounds__(NTHR, 1)
rnn_kernel(const float* __restrict__ x,   const float* __restrict__ Whx,
           const float* __restrict__ Whh, const float* __restrict__ Wph,
           const float* __restrict__ bh,  const float* __restrict__ bp,
           float* __restrict__ out)
{
    extern __shared__ char sm[];
    float* Xs   = (float*)(sm + SM_X);
    float* Hb0  = (float*)(sm + SM_H);
    float* Hb1  = Hb0 + BT * HD;
    float* rowsum = (float*)(sm + SM_RS);          // [128]
    unsigned* sflag = (unsigned*)(sm + SM_F);      // [2][8][2]
    unsigned* D0b   = (unsigned*)(sm + SM_F + 128);
    unsigned* D1b   = (unsigned*)(sm + SM_F + 132);
    unsigned* X1b   = (unsigned*)(sm + SM_F + 136);
    unsigned* xmaxb = (unsigned*)(sm + SM_F + 140);
    int*      okpos = (int*)(sm + SM_F + 144);
    int*      okfrz = (int*)(sm + SM_F + 148);

    const int tid  = threadIdx.x;
    const int lane = tid & 31;
    const int wid  = tid >> 5;
    const int pair = wid >> 1;                 // 0..7: owns cols 4*pair..+3
    const int half = wid & 1;                  // m half
    const int mb   = half * 64 + 2 * lane;     // this thread's m pair
    const int b0   = blockIdx.x * BT;

    if (tid == 0) {
        *D0b = 0u; *D1b = 0u; *X1b = 0x7f800000u;  // +inf
        *xmaxb = 0u; *okpos = 1; *okfrz = 1;
    }
    __syncthreads();

    // ---- Whh -> Ws[m][k] swizzled; rowsums via warp reduce; nonneg ----
    {
        bool nonneg = true;
        #pragma unroll
        for (int it = 0; it < 8; ++it) {
            const int m = wid + it * 16;                  // warp owns row m
            const float4 v = *(const float4*)(Whh + (size_t)m * HD + 4 * lane);
            nonneg &= (v.x >= 0.f) & (v.y >= 0.f) & (v.z >= 0.f) & (v.w >= 0.f);
            // one STS.128 at swizzled 16B slot (lane ^ ((m>>1)&15))
            *(float4*)(sm + SM_W + m * 512 +
                       ((lane ^ ((m >> 1) & 15)) << 4)) = v;
            float s = (v.x + v.y) + (v.z + v.w);
            #pragma unroll
            for (int o = 16; o > 0; o >>= 1)
                s += __shfl_xor_sync(0xffffffffu, s, o);
            if (lane == 0) rowsum[m] = s;
        }
        if (!__syncthreads_and(nonneg ? 1 : 0)) {
            if (tid == 0) atomicAnd(okpos, 0);
        }
    }
    // ---- x: streaming max over all t (MLP 8); store t < TPREF ----
    {
        float lm = 0.0f;
        #pragma unroll
        for (int it = 0; it < 8; ++it) {
            int i = tid + it * NTHR;
            int b = i >> 7, tq = i & 127;
            float4 v = *(const float4*)(x + (size_t)(b0 + b) * TS + 4 * tq);
            lm = fmaxf(lm, fmaxf(fmaxf(fabsf(v.x), fabsf(v.y)),
                                 fmaxf(fabsf(v.z), fabsf(v.w))));
            if (tq < TPREF / 4)
                *(float4*)(Xs + b * TPREF + 4 * tq) = v;
        }
        #pragma unroll
        for (int o = 16; o > 0; o >>= 1)                 // warp pre-reduction
            lm = fmaxf(lm, __shfl_xor_sync(0xffffffffu, lm, o));
        if (lane == 0)
            atomicMax(xmaxb, __float_as_uint(lm));       // |x| bits order-preserving
    }
    __syncthreads();

    // ---- certificate constants ----
    // D0 = max_m (TSAT+|bh_m|)/rowsum_m ; D1 = max_m |Whx_m|/rowsum_m
    // X1 = min_m (rowsum_m-|bh_m|-TSAT)/|Whx_m| (persistence bound for +-1)
    if (tid < HD) {
        int m = tid;
        float rs  = rowsum[m];
        float abh = fabsf(bh[m]), awx = fabsf(Whx[m]);
        if (rs <= 0.0f) {
            atomicAnd(okfrz, 0);
        } else {
            atomicMax(D0b, __float_as_uint((TSAT + abh) / rs));
            atomicMax(D1b, __float_as_uint(awx / rs));
            float num = rs - abh - TSAT;
            if (num <= 0.0f) atomicAnd(okfrz, 0);
            else {
                float X1m = (awx > 0.0f) ? num / awx : 3.0e38f;
                atomicMin(X1b, __float_as_uint(X1m));    // positive floats
            }
        }
    }
    __syncthreads();
    const float D0v = __uint_as_float(*D0b);
    const float D1v = __uint_as_float(*D1b);
    const bool  retire_ok = (*okpos != 0) && (*okfrz != 0) &&
                            (__uint_as_float(*xmaxb) <= __uint_as_float(*X1b));

    const float2 wxv = *(const float2*)(Whx + mb);
    const float2 bhv = *(const float2*)(bh  + mb);
    const char* Wp = sm + SM_W + mb * 512;               // thread's row base
    const uint32_t wsw = ((uint32_t)(lane & 15)) << 4;   // swizzle = (mb>>1)&15

    // ================= per-pair recurrence (named-barrier scoped) =================
    int cols[4] = {4 * pair, 4 * pair + 1, 4 * pair + 2, 4 * pair + 3};
    int nact = 4, cur = 0;
    int padc = 4 * pair;    // a retired column of THIS pair (valid when used)

    // x register carry: xv = x_t, xn = x_{t+1} (drives threshold), xf = x_{t+2}
    float xv[4], xn[4];
    #pragma unroll
    for (int j = 0; j < 4; ++j) {
        xv[j] = Xs[(4 * pair + j) * TPREF + 0];
        xn[j] = Xs[(4 * pair + j) * TPREF + 1];
    }

    for (int t = 0; t < TS && nact > 0; ++t) {
        const float* hrd = (cur == 0) ? Hb0 : Hb1;
        float*       hwr = (cur == 0) ? Hb1 : Hb0;

        // thresholds from carried registers — no loads on this path
        float thrj[4] = {1.f, 1.f, 1.f, 1.f};
        #pragma unroll
        for (int j = 0; j < 4; ++j)
            if (j < nact)
                thrj[j] = retire_ok ? fminf(fmaf(D1v, fabsf(xn[j]), D0v), 1.0f)
                                    : 1.0f;
        unsigned am;
        if (t == 0) {
            // h0 = 0: h1 = tanh(Whx*x0 + bh), no GEMV
            ull a[4];
            #pragma unroll
            for (int j = 0; j < 4; ++j)
                a[j] = pk(fmaf(wxv.x, xv[j], bhv.x), fmaf(wxv.y, xv[j], bhv.y));
            am = epilogue<4>(a, hwr, cols, mb, thrj);
        } else switch (nact) {
            // nact==3 runs J=4 with slot 3 padded by a retired column of this
            // pair: its h is uniform +-1 in BOTH buffers and the persistence
            // cert guarantees the recompute reproduces exactly the same +-1,
            // so the extra work is idempotent (vote bit masked by nact).
            case 4: case 3:
                    am = do_step<4>(Wp, wsw, hrd, hwr, cols, xv,
                                    wxv.x, wxv.y, bhv.x, bhv.y, mb, thrj); break;
            case 2: am = do_step<2>(Wp, wsw, hrd, hwr, cols, xv,
                                    wxv.x, wxv.y, bhv.x, bhv.y, mb, thrj); break;
            default: am = do_step<1>(Wp, wsw, hrd, hwr, cols, xv,
                                    wxv.x, wxv.y, bhv.x, bhv.y, mb, thrj); break;
        }

        if (lane == 0) sflag[(t & 1) * 16 + pair * 2 + half] = am;

        // prefetch x_{t+2} BEFORE the barrier (independent of h buffers);
        // its latency (incl. the __ldg tail) hides behind the barrier wait.
        float xf[4] = {0.f, 0.f, 0.f, 0.f};
        {
            int t2 = t + 2;
            if (t2 < TS) {
                #pragma unroll
                for (int j = 0; j < 4; ++j)
                    if (j < nact) {
                        int c = cols[j];
                        xf[j] = (t2 < TPREF) ? Xs[c * TPREF + t2]
                                             : __ldg(x + (size_t)(b0 + c) * TS + t2);
                    }
            }
        }

        asm volatile("bar.sync %0, 64;" :: "r"(1 + pair) : "memory");
        uint2 fl = *(const uint2*)(sflag + (t & 1) * 16 + pair * 2);
        unsigned f0 = fl.x, f1 = fl.y;
        cur ^= 1;

        // uniform h >= thr (or <= -thr) across ALL 128 m  =>  next state is
        // exactly uniform +-1 (per-step cert via thr) and stays (Xmax <= X1).
        if (retire_ok && t < TS - 1) {
            unsigned amp = f0 & f1 & 0xFu;
            unsigned amn = (f0 >> 8) & (f1 >> 8) & 0xFu;
            unsigned ab  = (amp | amn) & ((1u << nact) - 1u);
            if (ab) {
                #pragma unroll
                for (int j = 0; j < 4; ++j)
                    if (j < nact && ((ab >> j) & 1u)) {
                        float s = ((amp >> j) & 1u) ? 1.0f : -1.0f;
                        float2 sv = make_float2(s, s);
                        *(float2*)(Hb0 + cols[j] * HD + mb) = sv;
                        *(float2*)(Hb1 + cols[j] * HD + mb) = sv;
                        padc = cols[j];
                    }
                int nn = 0, nc[4];
                float nxn[4], nxf[4];
                #pragma unroll
                for (int j = 0; j < 4; ++j)
                    if (j < nact && !((ab >> j) & 1u)) {
                        nc[nn] = cols[j]; nxn[nn] = xn[j]; nxf[nn] = xf[j];
                        ++nn;
                    }
                nact = nn;
                #pragma unroll
                for (int j = 0; j < 4; ++j) {
                    cols[j] = (j < nn) ? nc[j] : padc;      // pad: idempotent
                    xn[j]   = (j < nn) ? nxn[j] : 0.0f;     // pad: x = 0 (cert ok)
                    xf[j]   = (j < nn) ? nxf[j] : 0.0f;
                }
            }
        }
        // advance the x carry
        #pragma unroll
        for (int j = 0; j < 4; ++j) { xv[j] = xn[j]; xn[j] = xf[j]; }
    }
    // make pair-mate's post-barrier sign writes visible before projection
    asm volatile("bar.sync %0, 64;" :: "r"(1 + pair) : "memory");

    // ================= projection: warp handles 2 of its pair's columns =================
    const float* hf = (cur == 0) ? Hb0 : Hb1;
    {
        int c0 = 4 * pair + 2 * half, c1 = c0 + 1;
        const float4 h0q = *(const float4*)(hf + c0 * HD + 4 * lane);
        const float4 h1q = *(const float4*)(hf + c1 * HD + 4 * lane);
        #pragma unroll
        for (int cls = 0; cls < CD; ++cls) {
            const float4 wq = __ldg((const float4*)(Wph + cls * HD) + lane);
            float s0 = h0q.x * wq.x + h0q.y * wq.y + h0q.z * wq.z + h0q.w * wq.w;
            float s1 = h1q.x * wq.x + h1q.y * wq.y + h1q.z * wq.z + h1q.w * wq.w;
            #pragma unroll
            for (int o = 16; o > 0; o >>= 1) {
                s0 += __shfl_xor_sync(0xffffffffu, s0, o);
                s1 += __shfl_xor_sync(0xffffffffu, s1, o);
            }
            if (lane == 0) {
                float bpv = __ldg(bp + cls);
                out[(size_t)(b0 + c0) * CD + cls] = s0 + bpv;
                out[(size_t)(b0 + c1) * CD + cls] = s1 + bpv;
            }
        }
    }
}

extern "C" void kernel_launch(void* const* d_in, const int* in_sizes, int n_in,
                              void* d_out, int out_size) {
    const float* x   = (const float*)d_in[0];
    const float* Whx = (const float*)d_in[1];
    const float* Whh = (const float*)d_in[2];
    const float* Wph = (const float*)d_in[3];
    const float* bh  = (const float*)d_in[4];
    const float* bp  = (const float*)d_in[5];
    cudaFuncSetAttribute(rnn_kernel, cudaFuncAttributeMaxDynamicSharedMemorySize, SM_SZ);
    rnn_kernel<<<NCTA, NTHR, SM_SZ>>>(x, Whx, Whh, Wph, bh, bp, (float*)d_out);
}

// round 15
// speedup vs baseline: 1.0861x; 1.0861x over previous
#include <cuda_runtime.h>
#include <cstdint>

#define HD   128
#define TS   512
#define BSZ  4096
#define CD   10
#define BT   32
#define NCTA (BSZ / BT)   // 128
#define NTHR 512          // 16 warps = 8 pairs; pair p owns cols 4p..4p+3
#define TPREF 128
#define TSAT 9.2f         // fp32 tanhf(x) == 1.0f for x >= ~9.01 (margin kept)

// ---- shared memory layout (bytes) ----
#define SM_W    0                    // W[m][k] swizzled, row 512B : 64 KB
#define SM_X    (64 * 1024)          // xs[32][TPREF]              : 16 KB
#define SM_H    (80 * 1024)          // h[2][32][128] ping-pong    : 32 KB
#define SM_RS   (112 * 1024)         // rowsum[128]                : 512 B
#define SM_F    (SM_RS + 512)        // sflag, cert scalars
#define SM_SZ   (SM_F + 256)

typedef unsigned long long ull;

static __device__ __forceinline__ ull pk(float lo, float hi) {
    ull r; asm("mov.b64 %0, {%1, %2};" : "=l"(r) : "f"(lo), "f"(hi)); return r;
}
static __device__ __forceinline__ void upk(ull v, float& lo, float& hi) {
    asm("mov.b64 {%0, %1}, %2;" : "=f"(lo), "=f"(hi) : "l"(v));
}
static __device__ __forceinline__ ull fma2(ull a, ull b, ull c) {
    ull d; asm("fma.rn.f32x2 %0, %1, %2, %3;" : "=l"(d) : "l"(a), "l"(b), "l"(c)); return d;
}
static __device__ __forceinline__ ull add2(ull a, ull b) {
    ull d; asm("add.rn.f32x2 %0, %1, %2;" : "=l"(d) : "l"(a), "l"(b)); return d;
}
// exactly +-1.0f for |x| >~ 9 (matches fp32 tanhf saturation); ~1e-7 abs err
// __fdividef: 2/(inf) -> 0, so saturation to exactly 1.0f is preserved.
static __device__ __forceinline__ float tanh_acc(float v) {
    float a = fabsf(v);
    float e = __expf(2.0f * a);
    float r = 1.0f - __fdividef(2.0f, e + 1.0f);
    return copysignf(r, v);
}

// epilogue: tanh, float2 write of this half's m-pair, per-col threshold
// votes. am bits: j -> all v >= thr[j] ; 8+j -> all v <= -thr[j]
template <int J>
static __device__ __forceinline__ unsigned
epilogue(const ull* acc, float* hwr, const int* cols, int mb, const float* thr)
{
    unsigned am = 0;
    #pragma unroll
    for (int j = 0; j < J; ++j) {
        float v0, v1; upk(acc[j], v0, v1);
        v0 = tanh_acc(v0); v1 = tanh_acc(v1);
        *(float2*)(hwr + cols[j] * HD + mb) = make_float2(v0, v1);
        bool p = (v0 >=  thr[j]) & (v1 >=  thr[j]);
        bool n = (v0 <= -thr[j]) & (v1 <= -thr[j]);
        unsigned bp_ = __ballot_sync(0xffffffffu, p);
        unsigned bn_ = __ballot_sync(0xffffffffu, n);
        if (bp_ == 0xffffffffu) am |= 1u << j;
        if (bn_ == 0xffffffffu) am |= 1u << (8 + j);
    }
    return am;
}

// one step for J live columns; this warp covers m = mb, mb+1 (its half).
// k-vectorized: acc lanes are (even-k, odd-k) partial sums; horizontal add
// at the end. The x-term + bias fold in AT THE END, so the loop-top x-loads
// hide behind the whole GEMV. J=2: 2 chains; J=1: 4 chains.
template <int J>
static __device__ __forceinline__ unsigned
do_step(const char* Wp, uint32_t wsw, const float* hrd, float* hwr,
        const int* cols, const float* xv,
        float wx0, float wx1, float bh0, float bh1, int mb, const float* thr)
{
    constexpr int CH = (J == 1) ? 4 : ((J == 2) ? 2 : 1);
    ull a0[J][CH], a1[J][CH];          // rows mb, mb+1
    const float* hc[J];
    #pragma unroll
    for (int j = 0; j < J; ++j) {
        #pragma unroll
        for (int c = 0; c < CH; ++c) { a0[j][c] = 0ull; a1[j][c] = 0ull; }
        hc[j] = hrd + cols[j] * HD;
    }
    #pragma unroll 4
    for (int k4 = 0; k4 < 32; ++k4) {
        const int ch = k4 & (CH - 1);
        const uint32_t woff = ((uint32_t)(k4 << 4)) ^ wsw;   // swizzled 16B slot
        const ulonglong2 w0 = *(const ulonglong2*)(Wp + woff);        // row mb
        const ulonglong2 w1 = *(const ulonglong2*)(Wp + 512 + woff);  // row mb+1
        #pragma unroll
        for (int j = 0; j < J; ++j) {
            const ulonglong2 h = *(const ulonglong2*)(hc[j] + 4 * k4); // bcast
            a0[j][ch] = fma2(w0.x, h.x, a0[j][ch]);
            a0[j][ch] = fma2(w0.y, h.y, a0[j][ch]);
            a1[j][ch] = fma2(w1.x, h.x, a1[j][ch]);
            a1[j][ch] = fma2(w1.y, h.y, a1[j][ch]);
        }
    }
    ull fin[J];
    #pragma unroll
    for (int j = 0; j < J; ++j) {
        ull f0 = a0[j][0], f1 = a1[j][0];
        #pragma unroll
        for (int c = 1; c < CH; ++c) { f0 = add2(f0, a0[j][c]); f1 = add2(f1, a1[j][c]); }
        float p0, p1, q0, q1;
        upk(f0, p0, p1); upk(f1, q0, q1);
        // fold x-term + bias here (loads long since landed)
        fin[j] = pk((p0 + p1) + fmaf(wx0, xv[j], bh0),
                    (q0 + q1) + fmaf(wx1, xv[j], bh1));
    }
    return epilogue<J>(fin, hwr, cols, mb, thr);
}

__global__ void __launch_bounds__(NTHR, 1)
rnn_kernel(const float* __restrict__ x,   const float* __restrict__ Whx,
           const float* __restrict__ Whh, const float* __restrict__ Wph,
           const float* __restrict__ bh,  const float* __restrict__ bp,
           float* __restrict__ out)
{
    extern __shared__ char sm[];
    float* Xs   = (float*)(sm + SM_X);
    float* Hb0  = (float*)(sm + SM_H);
    float* Hb1  = Hb0 + BT * HD;
    float* rowsum = (float*)(sm + SM_RS);          // [128]
    unsigned* sflag = (unsigned*)(sm + SM_F);      // [2][8][2]
    unsigned* D0b   = (unsigned*)(sm + SM_F + 128);
    unsigned* D1b   = (unsigned*)(sm + SM_F + 132);
    unsigned* X1b   = (unsigned*)(sm + SM_F + 136);
    unsigned* xmaxb = (unsigned*)(sm + SM_F + 140);
    int*      okpos = (int*)(sm + SM_F + 144);
    int*      okfrz = (int*)(sm + SM_F + 148);

    const int tid  = threadIdx.x;
    const int lane = tid & 31;
    const int wid  = tid >> 5;
    const int pair = wid >> 1;                 // 0..7: owns cols 4*pair..+3
    const int half = wid & 1;                  // m half
    const int mb   = half * 64 + 2 * lane;     // this thread's m pair
    const int b0   = blockIdx.x * BT;

    if (tid == 0) {
        *D0b = 0u; *D1b = 0u; *X1b = 0x7f800000u;  // +inf
        *xmaxb = 0u; *okpos = 1; *okfrz = 1;
    }
    __syncthreads();

    // ---- Whh -> Ws[m][k] swizzled; rowsums via warp reduce; nonneg ----
    {
        bool nonneg = true;
        #pragma unroll
        for (int it = 0; it < 8; ++it) {
            const int m = wid + it * 16;                  // warp owns row m
            const float4 v = *(const float4*)(Whh + (size_t)m * HD + 4 * lane);
            nonneg &= (v.x >= 0.f) & (v.y >= 0.f) & (v.z >= 0.f) & (v.w >= 0.f);
            // one STS.128 at swizzled 16B slot (lane ^ ((m>>1)&15))
            *(float4*)(sm + SM_W + m * 512 +
                       ((lane ^ ((m >> 1) & 15)) << 4)) = v;
            float s = (v.x + v.y) + (v.z + v.w);
            #pragma unroll
            for (int o = 16; o > 0; o >>= 1)
                s += __shfl_xor_sync(0xffffffffu, s, o);
            if (lane == 0) rowsum[m] = s;
        }
        if (!__syncthreads_and(nonneg ? 1 : 0)) {
            if (tid == 0) atomicAnd(okpos, 0);
        }
    }
    // ---- x: streaming max over all t (MLP 8); store t < TPREF ----
    {
        float lm = 0.0f;
        #pragma unroll
        for (int it = 0; it < 8; ++it) {
            int i = tid + it * NTHR;
            int b = i >> 7, tq = i & 127;
            float4 v = *(const float4*)(x + (size_t)(b0 + b) * TS + 4 * tq);
            lm = fmaxf(lm, fmaxf(fmaxf(fabsf(v.x), fabsf(v.y)),
                                 fmaxf(fabsf(v.z), fabsf(v.w))));
            if (tq < TPREF / 4)
                *(float4*)(Xs + b * TPREF + 4 * tq) = v;
        }
        #pragma unroll
        for (int o = 16; o > 0; o >>= 1)                 // warp pre-reduction
            lm = fmaxf(lm, __shfl_xor_sync(0xffffffffu, lm, o));
        if (lane == 0)
            atomicMax(xmaxb, __float_as_uint(lm));       // |x| bits order-preserving
    }
    __syncthreads();

    // ---- certificate constants ----
    // D0 = max_m (TSAT+|bh_m|)/rowsum_m ; D1 = max_m |Whx_m|/rowsum_m
    // X1 = min_m (rowsum_m-|bh_m|-TSAT)/|Whx_m| (persistence bound for +-1)
    if (tid < HD) {
        int m = tid;
        float rs  = rowsum[m];
        float abh = fabsf(bh[m]), awx = fabsf(Whx[m]);
        if (rs <= 0.0f) {
            atomicAnd(okfrz, 0);
        } else {
            atomicMax(D0b, __float_as_uint((TSAT + abh) / rs));
            atomicMax(D1b, __float_as_uint(awx / rs));
            float num = rs - abh - TSAT;
            if (num <= 0.0f) atomicAnd(okfrz, 0);
            else {
                float X1m = (awx > 0.0f) ? num / awx : 3.0e38f;
                atomicMin(X1b, __float_as_uint(X1m));    // positive floats
            }
        }
    }
    __syncthreads();
    const float D0v = __uint_as_float(*D0b);
    const float D1v = __uint_as_float(*D1b);
    const bool  retire_ok = (*okpos != 0) && (*okfrz != 0) &&
                            (__uint_as_float(*xmaxb) <= __uint_as_float(*X1b));

    const float2 wxv = *(const float2*)(Whx + mb);
    const float2 bhv = *(const float2*)(bh  + mb);
    const char* Wp = sm + SM_W + mb * 512;               // thread's row base
    const uint32_t wsw = ((uint32_t)(lane & 15)) << 4;   // swizzle = (mb>>1)&15

    // ================= per-pair recurrence (named-barrier scoped) =================
    int cols[4] = {4 * pair, 4 * pair + 1, 4 * pair + 2, 4 * pair + 3};
    int nact = 4, cur = 0;
    int padc = 4 * pair;    // a retired column of THIS pair (valid when used)

    for (int t = 0; t < TS && nact > 0; ++t) {
        const float* hrd = (cur == 0) ? Hb0 : Hb1;
        float*       hwr = (cur == 0) ? Hb1 : Hb0;

        // x-loads issued here are consumed only at the END of the GEMV /
        // in the epilogue votes — their latency hides behind the step.
        float xv[4]   = {0.f, 0.f, 0.f, 0.f};
        float thrj[4] = {1.f, 1.f, 1.f, 1.f};
        #pragma unroll
        for (int j = 0; j < 4; ++j)
            if (j < nact) {
                int c = cols[j];
                xv[j] = (t < TPREF) ? Xs[c * TPREF + t]
                                    : __ldg(x + (size_t)(b0 + c) * TS + t);
                float xn = 0.0f;                 // NEXT x drives the +-1 jump
                if (t + 1 < TS)
                    xn = (t + 1 < TPREF) ? Xs[c * TPREF + t + 1]
                                         : __ldg(x + (size_t)(b0 + c) * TS + t + 1);
                thrj[j] = retire_ok ? fminf(fmaf(D1v, fabsf(xn), D0v), 1.0f)
                                    : 1.0f;
            }
        unsigned am;
        if (t == 0) {
            // h0 = 0: h1 = tanh(Whx*x0 + bh), no GEMV
            ull a[4];
            #pragma unroll
            for (int j = 0; j < 4; ++j)
                a[j] = pk(fmaf(wxv.x, xv[j], bhv.x), fmaf(wxv.y, xv[j], bhv.y));
            am = epilogue<4>(a, hwr, cols, mb, thrj);
        } else switch (nact) {
            // nact==3 runs J=4 with slot 3 padded by a retired column of this
            // pair: its h is uniform +-1 in BOTH buffers and the persistence
            // cert guarantees the recompute reproduces exactly the same +-1,
            // so the extra work is idempotent (vote bit masked by nact).
            case 4: case 3:
                    am = do_step<4>(Wp, wsw, hrd, hwr, cols, xv,
                                    wxv.x, wxv.y, bhv.x, bhv.y, mb, thrj); break;
            case 2: am = do_step<2>(Wp, wsw, hrd, hwr, cols, xv,
                                    wxv.x, wxv.y, bhv.x, bhv.y, mb, thrj); break;
            default: am = do_step<1>(Wp, wsw, hrd, hwr, cols, xv,
                                    wxv.x, wxv.y, bhv.x, bhv.y, mb, thrj); break;
        }

        if (lane == 0) sflag[(t & 1) * 16 + pair * 2 + half] = am;
        asm volatile("bar.sync %0, 64;" :: "r"(1 + pair) : "memory");
        uint2 fl = *(const uint2*)(sflag + (t & 1) * 16 + pair * 2);
        unsigned f0 = fl.x, f1 = fl.y;
        cur ^= 1;

        // uniform h >= thr (or <= -thr) across ALL 128 m  =>  next state is
        // exactly uniform +-1 (per-step cert via thr) and stays (Xmax <= X1).
        if (retire_ok && t < TS - 1) {
            unsigned amp = f0 & f1 & 0xFu;
            unsigned amn = (f0 >> 8) & (f1 >> 8) & 0xFu;
            unsigned ab  = (amp | amn) & ((1u << nact) - 1u);
            if (ab) {
                #pragma unroll
                for (int j = 0; j < 4; ++j)
                    if (j < nact && ((ab >> j) & 1u)) {
                        float s = ((amp >> j) & 1u) ? 1.0f : -1.0f;
                        float2 sv = make_float2(s, s);
                        *(float2*)(Hb0 + cols[j] * HD + mb) = sv;
                        *(float2*)(Hb1 + cols[j] * HD + mb) = sv;
                        padc = cols[j];
                    }
                int nn = 0, nc[4];
                #pragma unroll
                for (int j = 0; j < 4; ++j)
                    if (j < nact && !((ab >> j) & 1u)) nc[nn++] = cols[j];
                nact = nn;
                #pragma unroll
                for (int j = 0; j < 4; ++j) cols[j] = (j < nn) ? nc[j] : padc;
            }
        }
    }
    // make pair-mate's post-barrier sign writes visible before projection
    asm volatile("bar.sync %0, 64;" :: "r"(1 + pair) : "memory");

    // ================= projection: warp handles 2 of its pair's columns =================
    const float* hf = (cur == 0) ? Hb0 : Hb1;
    {
        int c0 = 4 * pair + 2 * half, c1 = c0 + 1;
        const float4 h0q = *(const float4*)(hf + c0 * HD + 4 * lane);
        const float4 h1q = *(const float4*)(hf + c1 * HD + 4 * lane);
        #pragma unroll
        for (int cls = 0; cls < CD; ++cls) {
            const float4 wq = __ldg((const float4*)(Wph + cls * HD) + lane);
            float s0 = h0q.x * wq.x + h0q.y * wq.y + h0q.z * wq.z + h0q.w * wq.w;
            float s1 = h1q.x * wq.x + h1q.y * wq.y + h1q.z * wq.z + h1q.w * wq.w;
            #pragma unroll
            for (int o = 16; o > 0; o >>= 1) {
                s0 += __shfl_xor_sync(0xffffffffu, s0, o);
                s1 += __shfl_xor_sync(0xffffffffu, s1, o);
            }
            if (lane == 0) {
                float bpv = __ldg(bp + cls);
                out[(size_t)(b0 + c0) * CD + cls] = s0 + bpv;
                out[(size_t)(b0 + c1) * CD + cls] = s1 + bpv;
            }
        }
    }
}

extern "C" void kernel_launch(void* const* d_in, const int* in_sizes, int n_in,
                              void* d_out, int out_size) {
    const float* x   = (const float*)d_in[0];
    const float* Whx = (const float*)d_in[1];
    const float* Whh = (const float*)d_in[2];
    const float* Wph = (const float*)d_in[3];
    const float* bh  = (const float*)d_in[4];
    const float* bp  = (const float*)d_in[5];
    cudaFuncSetAttribute(rnn_kernel, cudaFuncAttributeMaxDynamicSharedMemorySize, SM_SZ);
    rnn_kernel<<<NCTA, NTHR, SM_SZ>>>(x, Whx, Whh, Wph, bh, bp, (float*)d_out);
}